// round 15
// baseline (speedup 1.0000x reference)
#include <cuda_runtime.h>
#include <cuda_fp16.h>
#include <cstdint>
#include <cstddef>

// y[8192,4096] = x @ sign(W)^T + bias. fp16 mma.sync GEMM, CTA 128x128x64,
// 4 warps (warp tile 64x64), reg-double-buffered fragments, 3-stage cp.async,
// 2 CTAs/SM, 1 barrier/iteration.
#define DIM_M 8192
#define DIM_N 4096
#define DIM_K 4096
#define BK 64
#define NCH (DIM_K / BK)            // 64
#define STG_BYTES 32768             // A 16K + B 16K
#define SMEM_TOTAL (3 * STG_BYTES)  // 96 KB -> 2 CTAs/SM

__device__ __half g_xh[(size_t)DIM_M * DIM_K];   // 64 MB
__device__ __half g_wb[(size_t)DIM_N * DIM_K];   // 32 MB

__device__ __forceinline__ uint32_t smem_u32(const void* p) {
    uint32_t a;
    asm("{ .reg .u64 t; cvta.to.shared.u64 t, %1; cvt.u32.u64 %0, t; }" : "=r"(a) : "l"(p));
    return a;
}
__device__ __forceinline__ uint32_t swz(uint32_t off) { return off ^ ((off >> 3) & 0x70); }
__device__ __forceinline__ void cp16(uint32_t dst, const void* src) {
    asm volatile("cp.async.cg.shared.global [%0], [%1], 16;" :: "r"(dst), "l"(src));
}
__device__ __forceinline__ void ldm4(uint32_t* r, uint32_t addr) {
    asm volatile("ldmatrix.sync.aligned.m8n8.x4.shared.b16 {%0,%1,%2,%3}, [%4];"
                 : "=r"(r[0]), "=r"(r[1]), "=r"(r[2]), "=r"(r[3]) : "r"(addr));
}
__device__ __forceinline__ void mma16816(float* d, const uint32_t* a,
                                         uint32_t b0, uint32_t b1) {
    asm volatile(
        "mma.sync.aligned.m16n8k16.row.col.f32.f16.f16.f32 "
        "{%0,%1,%2,%3}, {%4,%5,%6,%7}, {%8,%9}, {%0,%1,%2,%3};"
        : "+f"(d[0]), "+f"(d[1]), "+f"(d[2]), "+f"(d[3])
        : "r"(a[0]), "r"(a[1]), "r"(a[2]), "r"(a[3]), "r"(b0), "r"(b1));
}

__device__ __forceinline__ void load_chunk(uint32_t stage, int m0, int n0, int k0, int tid) {
    const __half* xa = g_xh + (size_t)m0 * DIM_K + k0;
    const __half* wb = g_wb + (size_t)n0 * DIM_K + k0;
    #pragma unroll
    for (int i = tid; i < 1024; i += 128) {          // 128 rows x 8 x 16B each
        int r = i >> 3, c = i & 7;
        uint32_t d = swz((uint32_t)(r * 128 + c * 16));
        cp16(stage + d, xa + (size_t)r * DIM_K + c * 8);
        cp16(stage + 16384 + d, wb + (size_t)r * DIM_K + c * 8);
    }
}

__global__ void __launch_bounds__(128, 2)
binlin_gemm(const float* __restrict__ bias, float* __restrict__ out) {
    extern __shared__ char smem[];
    const int tid = threadIdx.x, lane = tid & 31, w = tid >> 5;
    const int wm = w >> 1, wn = w & 1;               // 2(m) x 2(n); warp = 64x64
    const int m0 = blockIdx.y * 128, n0 = blockIdx.x * 128;
    const uint32_t sb = smem_u32(smem);

    float acc[4][8][4];
    #pragma unroll
    for (int i = 0; i < 4; ++i)
        #pragma unroll
        for (int j = 0; j < 8; ++j)
            #pragma unroll
            for (int t = 0; t < 4; ++t) acc[i][j][t] = 0.f;

    load_chunk(sb, m0, n0, 0, tid);
    asm volatile("cp.async.commit_group;" ::: "memory");
    load_chunk(sb + STG_BYTES, m0, n0, BK, tid);
    asm volatile("cp.async.commit_group;" ::: "memory");

    const int lrow = lane & 15, lkh = lane >> 4;
    uint32_t abase[4], bbase[4];
    #pragma unroll
    for (int mt = 0; mt < 4; ++mt)
        abase[mt] = (uint32_t)((wm * 64 + mt * 16 + lrow) * 128);
    #pragma unroll
    for (int nt = 0; nt < 4; ++nt)
        bbase[nt] = (uint32_t)((wn * 64 + nt * 16 + lrow) * 128);

    uint32_t a[2][4][4], b[2][4][4];                 // double-buffered fragments

    for (int c = 0; c < NCH; ++c) {
        if (c < NCH - 1) { asm volatile("cp.async.wait_group 1;" ::: "memory"); }
        else            { asm volatile("cp.async.wait_group 0;" ::: "memory"); }
        __syncthreads();   // stage c ready; also fences stage (c-1)%3 reads
        if (c + 2 < NCH) {
            load_chunk(sb + ((c + 2) % 3) * STG_BYTES, m0, n0, (c + 2) * BK, tid);
            asm volatile("cp.async.commit_group;" ::: "memory");
        }
        const uint32_t sa = sb + (c % 3) * STG_BYTES;
        const uint32_t sB = sa + 16384;
        {   // prime ks=0 fragments
            const uint32_t kb = (uint32_t)(lkh * 16);
            #pragma unroll
            for (int mt = 0; mt < 4; ++mt) ldm4(a[0][mt], sa + swz(abase[mt] + kb));
            #pragma unroll
            for (int nt = 0; nt < 4; ++nt) ldm4(b[0][nt], sB + swz(bbase[nt] + kb));
        }
        #pragma unroll
        for (int ks = 0; ks < 4; ++ks) {
            const int cur = ks & 1, nxt = cur ^ 1;
            if (ks < 3) {  // prefetch ks+1 while MMAs of ks issue
                const uint32_t kb = (uint32_t)((ks + 1) * 32 + lkh * 16);
                #pragma unroll
                for (int mt = 0; mt < 4; ++mt) ldm4(a[nxt][mt], sa + swz(abase[mt] + kb));
                #pragma unroll
                for (int nt = 0; nt < 4; ++nt) ldm4(b[nxt][nt], sB + swz(bbase[nt] + kb));
            }
            #pragma unroll
            for (int mt = 0; mt < 4; ++mt)
                #pragma unroll
                for (int nt = 0; nt < 4; ++nt) {
                    mma16816(acc[mt][nt * 2 + 0], a[cur][mt], b[cur][nt][0], b[cur][nt][2]);
                    mma16816(acc[mt][nt * 2 + 1], a[cur][mt], b[cur][nt][1], b[cur][nt][3]);
                }
        }
    }

    // Epilogue: m = m0 + wm*64 + mt*16 + lane/4 (+8), n = n0 + wn*64 + (j>>1)*16 + (j&1)*8
    float2 bv[8];
    #pragma unroll
    for (int j = 0; j < 8; ++j)
        bv[j] = *(const float2*)&bias[n0 + wn * 64 + (j >> 1) * 16 + (j & 1) * 8 + (lane & 3) * 2];
    #pragma unroll
    for (int mt = 0; mt < 4; ++mt) {
        const int mrow = m0 + wm * 64 + mt * 16 + (lane >> 2);
        #pragma unroll
        for (int j = 0; j < 8; ++j) {
            const int gn = n0 + wn * 64 + (j >> 1) * 16 + (j & 1) * 8 + (lane & 3) * 2;
            float2 v0 = make_float2(acc[mt][j][0] + bv[j].x, acc[mt][j][1] + bv[j].y);
            float2 v1 = make_float2(acc[mt][j][2] + bv[j].x, acc[mt][j][3] + bv[j].y);
            *(float2*)&out[(size_t)mrow * DIM_N + gn] = v0;
            *(float2*)&out[(size_t)(mrow + 8) * DIM_N + gn] = v1;
        }
    }
}

// Fused convert: x -> fp16 (rn), W -> sign(W) fp16.
#define N4X ((size_t)DIM_M * DIM_K / 4)
#define N4W ((size_t)DIM_N * DIM_K / 4)
__global__ void conv_all(const float4* __restrict__ x, const float4* __restrict__ w) {
    uint2* px = (uint2*)g_xh;
    ushort4* pw = (ushort4*)g_wb;
    for (size_t i = (size_t)blockIdx.x * blockDim.x + threadIdx.x; i < N4X + N4W;
         i += (size_t)gridDim.x * blockDim.x) {
        if (i < N4X) {
            float4 v = x[i];
            __half2 lo = __floats2half2_rn(v.x, v.y);
            __half2 hi = __floats2half2_rn(v.z, v.w);
            uint2 o;
            o.x = *(uint32_t*)&lo;
            o.y = *(uint32_t*)&hi;
            px[i] = o;
        } else {
            size_t j = i - N4X;
            float4 v = w[j];
            ushort4 o;
            o.x = (v.x >= 0.f) ? 0x3C00 : 0xBC00;
            o.y = (v.y >= 0.f) ? 0x3C00 : 0xBC00;
            o.z = (v.z >= 0.f) ? 0x3C00 : 0xBC00;
            o.w = (v.w >= 0.f) ? 0x3C00 : 0xBC00;
            pw[j] = o;
        }
    }
}

extern "C" void kernel_launch(void* const* d_in, const int* in_sizes, int n_in,
                              void* d_out, int out_size) {
    const float* x = (const float*)d_in[0];
    const float* w = (const float*)d_in[1];
    const float* bias = (const float*)d_in[2];
    float* out = (float*)d_out;
    conv_all<<<3072, 256>>>((const float4*)x, (const float4*)w);
    cudaFuncSetAttribute(binlin_gemm, cudaFuncAttributeMaxDynamicSharedMemorySize, SMEM_TOTAL);
    dim3 grid(DIM_N / 128, DIM_M / 128);   // 32 x 64 = 2048 CTAs
    binlin_gemm<<<grid, 128, SMEM_TOTAL>>>(bias, out);
}

// round 16
// speedup vs baseline: 1.0164x; 1.0164x over previous
#include <cuda_runtime.h>
#include <cuda_fp16.h>
#include <cstdint>
#include <cstddef>

// y[8192,4096] = x @ sign(W)^T + bias. fp16 mma.sync GEMM, 128x128x64 tiles,
// 256 threads (8 warps, warp tile 32x64), 3-stage cp.async, mid-chunk load issue.
#define DIM_M 8192
#define DIM_N 4096
#define DIM_K 4096
#define BK 64
#define NCH (DIM_K / BK)            // 64
#define STG_BYTES 32768             // A 16K + B 16K
#define SMEM_TOTAL (3 * STG_BYTES)  // 96 KB -> 2 CTAs/SM

__device__ __half g_xh[(size_t)DIM_M * DIM_K];   // 64 MB
__device__ __half g_wb[(size_t)DIM_N * DIM_K];   // 32 MB

__device__ __forceinline__ uint32_t smem_u32(const void* p) {
    uint32_t a;
    asm("{ .reg .u64 t; cvta.to.shared.u64 t, %1; cvt.u32.u64 %0, t; }" : "=r"(a) : "l"(p));
    return a;
}
__device__ __forceinline__ uint32_t swz(uint32_t off) { return off ^ ((off >> 3) & 0x70); }
__device__ __forceinline__ void cp16(uint32_t dst, const void* src) {
    asm volatile("cp.async.cg.shared.global [%0], [%1], 16;" :: "r"(dst), "l"(src));
}
__device__ __forceinline__ void ldm4(uint32_t* r, uint32_t addr) {
    asm volatile("ldmatrix.sync.aligned.m8n8.x4.shared.b16 {%0,%1,%2,%3}, [%4];"
                 : "=r"(r[0]), "=r"(r[1]), "=r"(r[2]), "=r"(r[3]) : "r"(addr));
}
__device__ __forceinline__ void mma16816(float* d, const uint32_t* a,
                                         uint32_t b0, uint32_t b1) {
    asm volatile(
        "mma.sync.aligned.m16n8k16.row.col.f32.f16.f16.f32 "
        "{%0,%1,%2,%3}, {%4,%5,%6,%7}, {%8,%9}, {%0,%1,%2,%3};"
        : "+f"(d[0]), "+f"(d[1]), "+f"(d[2]), "+f"(d[3])
        : "r"(a[0]), "r"(a[1]), "r"(a[2]), "r"(a[3]), "r"(b0), "r"(b1));
}

__device__ __forceinline__ void load_chunk(uint32_t stage, int m0, int n0, int k0, int tid) {
    const __half* xa = g_xh + (size_t)m0 * DIM_K + k0;
    const __half* wb = g_wb + (size_t)n0 * DIM_K + k0;
    #pragma unroll
    for (int i = tid; i < 1024; i += 256) {          // 128 rows x 8 x 16B each
        int r = i >> 3, c = i & 7;
        uint32_t d = swz((uint32_t)(r * 128 + c * 16));
        cp16(stage + d, xa + (size_t)r * DIM_K + c * 8);
        cp16(stage + 16384 + d, wb + (size_t)r * DIM_K + c * 8);
    }
}

__global__ void __launch_bounds__(256, 2)
binlin_gemm(const float* __restrict__ bias, float* __restrict__ out) {
    extern __shared__ char smem[];
    const int tid = threadIdx.x, lane = tid & 31, w = tid >> 5;
    const int wm = w & 3, wn = w >> 2;               // 4(m) x 2(n); warp = 32x64
    const int m0 = blockIdx.y * 128, n0 = blockIdx.x * 128;
    const uint32_t sb = smem_u32(smem);

    float acc[2][8][4];
    #pragma unroll
    for (int i = 0; i < 2; ++i)
        #pragma unroll
        for (int j = 0; j < 8; ++j)
            #pragma unroll
            for (int t = 0; t < 4; ++t) acc[i][j][t] = 0.f;

    load_chunk(sb, m0, n0, 0, tid);
    asm volatile("cp.async.commit_group;" ::: "memory");
    load_chunk(sb + STG_BYTES, m0, n0, BK, tid);
    asm volatile("cp.async.commit_group;" ::: "memory");

    const int lrow = lane & 15, lkh = lane >> 4;
    uint32_t abase[2], bbase[4];
    #pragma unroll
    for (int mt = 0; mt < 2; ++mt)
        abase[mt] = (uint32_t)((wm * 32 + mt * 16 + lrow) * 128);
    #pragma unroll
    for (int nt = 0; nt < 4; ++nt)
        bbase[nt] = (uint32_t)((wn * 64 + nt * 16 + lrow) * 128);

    for (int c = 0; c < NCH; ++c) {
        __syncthreads();   // all warps done reading stage (c-1)%3
        if (c + 1 < NCH) { asm volatile("cp.async.wait_group 1;" ::: "memory"); }
        else            { asm volatile("cp.async.wait_group 0;" ::: "memory"); }
        __syncthreads();   // chunk c visible to all threads
        const uint32_t sa = sb + (c % 3) * STG_BYTES;
        const uint32_t sB = sa + 16384;
        #pragma unroll
        for (int ks = 0; ks < 4; ++ks) {
            const uint32_t kb = (uint32_t)(ks * 32 + lkh * 16);
            uint32_t a[2][4], b[4][4];
            #pragma unroll
            for (int mt = 0; mt < 2; ++mt)
                ldm4(a[mt], sa + swz(abase[mt] + kb));
            #pragma unroll
            for (int nt = 0; nt < 4; ++nt)
                ldm4(b[nt], sB + swz(bbase[nt] + kb));
            #pragma unroll
            for (int mt = 0; mt < 2; ++mt)
                #pragma unroll
                for (int nt = 0; nt < 4; ++nt) {
                    mma16816(acc[mt][nt * 2 + 0], a[mt], b[nt][0], b[nt][2]);
                    mma16816(acc[mt][nt * 2 + 1], a[mt], b[nt][1], b[nt][3]);
                }
            if (ks == 0 && c + 2 < NCH) {   // mid-chunk: issue next-next loads
                load_chunk(sb + ((c + 2) % 3) * STG_BYTES, m0, n0, (c + 2) * BK, tid);
                asm volatile("cp.async.commit_group;" ::: "memory");
            }
        }
    }

    // Epilogue: m = m0 + wm*32 + mt*16 + lane/4 (+8), n = n0 + wn*64 + ...
    float2 bv[8];
    #pragma unroll
    for (int j = 0; j < 8; ++j)
        bv[j] = *(const float2*)&bias[n0 + wn * 64 + (j >> 1) * 16 + (j & 1) * 8 + (lane & 3) * 2];
    #pragma unroll
    for (int mt = 0; mt < 2; ++mt) {
        const int mrow = m0 + wm * 32 + mt * 16 + (lane >> 2);
        #pragma unroll
        for (int j = 0; j < 8; ++j) {
            const int gn = n0 + wn * 64 + (j >> 1) * 16 + (j & 1) * 8 + (lane & 3) * 2;
            float2 v0 = make_float2(acc[mt][j][0] + bv[j].x, acc[mt][j][1] + bv[j].y);
            float2 v1 = make_float2(acc[mt][j][2] + bv[j].x, acc[mt][j][3] + bv[j].y);
            *(float2*)&out[(size_t)mrow * DIM_N + gn] = v0;
            *(float2*)&out[(size_t)(mrow + 8) * DIM_N + gn] = v1;
        }
    }
}

__global__ void conv_x(const float4* __restrict__ x) {
    const size_t n4 = (size_t)DIM_M * DIM_K / 4;
    const size_t S = (size_t)gridDim.x * blockDim.x;
    uint2* p = (uint2*)g_xh;
    for (size_t i = (size_t)blockIdx.x * blockDim.x + threadIdx.x; i < n4; i += 2 * S) {
        float4 v0 = x[i];
        float4 v1 = (i + S < n4) ? x[i + S] : make_float4(0, 0, 0, 0);
        __half2 a0 = __floats2half2_rn(v0.x, v0.y), a1 = __floats2half2_rn(v0.z, v0.w);
        __half2 b0 = __floats2half2_rn(v1.x, v1.y), b1 = __floats2half2_rn(v1.z, v1.w);
        uint2 o0, o1;
        o0.x = *(uint32_t*)&a0; o0.y = *(uint32_t*)&a1;
        o1.x = *(uint32_t*)&b0; o1.y = *(uint32_t*)&b1;
        p[i] = o0;
        if (i + S < n4) p[i + S] = o1;
    }
}

__global__ void conv_w(const float4* __restrict__ w) {
    const size_t n4 = (size_t)DIM_N * DIM_K / 4;
    const size_t S = (size_t)gridDim.x * blockDim.x;
    ushort4* p = (ushort4*)g_wb;
    for (size_t i = (size_t)blockIdx.x * blockDim.x + threadIdx.x; i < n4; i += 2 * S) {
        float4 v0 = w[i];
        float4 v1 = (i + S < n4) ? w[i + S] : make_float4(0, 0, 0, 0);
        ushort4 o0, o1;
        o0.x = (v0.x >= 0.f) ? 0x3C00 : 0xBC00;
        o0.y = (v0.y >= 0.f) ? 0x3C00 : 0xBC00;
        o0.z = (v0.z >= 0.f) ? 0x3C00 : 0xBC00;
        o0.w = (v0.w >= 0.f) ? 0x3C00 : 0xBC00;
        o1.x = (v1.x >= 0.f) ? 0x3C00 : 0xBC00;
        o1.y = (v1.y >= 0.f) ? 0x3C00 : 0xBC00;
        o1.z = (v1.z >= 0.f) ? 0x3C00 : 0xBC00;
        o1.w = (v1.w >= 0.f) ? 0x3C00 : 0xBC00;
        p[i] = o0;
        if (i + S < n4) p[i + S] = o1;
    }
}

extern "C" void kernel_launch(void* const* d_in, const int* in_sizes, int n_in,
                              void* d_out, int out_size) {
    const float* x = (const float*)d_in[0];
    const float* w = (const float*)d_in[1];
    const float* bias = (const float*)d_in[2];
    float* out = (float*)d_out;
    conv_x<<<2048, 256>>>((const float4*)x);
    conv_w<<<1024, 256>>>((const float4*)w);
    cudaFuncSetAttribute(binlin_gemm, cudaFuncAttributeMaxDynamicSharedMemorySize, SMEM_TOTAL);
    dim3 grid(DIM_N / 128, DIM_M / 128);   // 32 x 64 = 2048 CTAs
    binlin_gemm<<<grid, 256, SMEM_TOTAL>>>(bias, out);
}